// round 1
// baseline (speedup 1.0000x reference)
#include <cuda_runtime.h>

typedef unsigned long long u64;

__device__ __forceinline__ u64 pk2(float lo, float hi) {
    u64 r; asm("mov.b64 %0,{%1,%2};" : "=l"(r) : "f"(lo), "f"(hi)); return r;
}
__device__ __forceinline__ float2 up2(u64 v) {
    float2 f; asm("mov.b64 {%0,%1},%2;" : "=f"(f.x), "=f"(f.y) : "l"(v)); return f;
}
__device__ __forceinline__ u64 fma2(u64 a, u64 b, u64 c) {
    u64 d; asm("fma.rn.f32x2 %0,%1,%2,%3;" : "=l"(d) : "l"(a), "l"(b), "l"(c)); return d;
}
__device__ __forceinline__ u64 add2(u64 a, u64 b) {
    u64 d; asm("add.rn.f32x2 %0,%1,%2;" : "=l"(d) : "l"(a), "l"(b)); return d;
}
__device__ __forceinline__ u64 clamp2(u64 v) {
    float2 f = up2(v);
    f.x = fminf(fmaxf(f.x, -1.0f), 1.0f);
    f.y = fminf(fmaxf(f.y, -1.0f), 1.0f);
    return pk2(f.x, f.y);
}

// shared-memory u64 (duplicated-pair) layout
#define O_W1 0        // 648  (54x12)
#define O_B1 648      // 12
#define O_W2 660      // 144  (12x12)
#define O_B2 804      // 12
#define O_W3 816      // 48   (12x4)
#define O_B3 864      // 4
#define O_V1 868      // 4640 (145x32)
#define O_C1 5508     // 32
#define O_C2 5540     // 32
#define O_V3 5572     // 32
#define O_C3 5604     // 1
#define N_U64 5605    // 44840 bytes

__global__ void __launch_bounds__(128) lila_kernel(
    const float* __restrict__ inp,
    const float* __restrict__ W1, const float* __restrict__ b1,
    const float* __restrict__ W2, const float* __restrict__ b2,
    const float* __restrict__ W3, const float* __restrict__ b3,
    const float* __restrict__ V1, const float* __restrict__ c1,
    const float* __restrict__ V2, const float* __restrict__ c2,
    const float* __restrict__ V3, const float* __restrict__ c3,
    float* __restrict__ out, int nhalf)
{
    __shared__ u64  sw[N_U64];   // 44840 B (weights duplicated as {w,w})
    __shared__ float sV2[1024];  // 4096 B  (V2 kept scalar to fit 48KB static)

    // cooperative weight staging
    for (int i = threadIdx.x; i < 648;  i += 128) { float v = W1[i]; sw[O_W1+i] = pk2(v,v); }
    for (int i = threadIdx.x; i < 12;   i += 128) { float v = b1[i]; sw[O_B1+i] = pk2(v,v);
                                                    float u = b2[i]; sw[O_B2+i] = pk2(u,u); }
    for (int i = threadIdx.x; i < 144;  i += 128) { float v = W2[i]; sw[O_W2+i] = pk2(v,v); }
    for (int i = threadIdx.x; i < 48;   i += 128) { float v = W3[i]; sw[O_W3+i] = pk2(v,v); }
    for (int i = threadIdx.x; i < 4;    i += 128) { float v = b3[i]; sw[O_B3+i] = pk2(v,v); }
    for (int i = threadIdx.x; i < 4640; i += 128) { float v = V1[i]; sw[O_V1+i] = pk2(v,v); }
    for (int i = threadIdx.x; i < 32;   i += 128) { float v = c1[i]; sw[O_C1+i] = pk2(v,v);
                                                    float u = c2[i]; sw[O_C2+i] = pk2(u,u);
                                                    float w = V3[i]; sw[O_V3+i] = pk2(w,w); }
    for (int i = threadIdx.x; i < 1024; i += 128) { sV2[i] = V2[i]; }
    if (threadIdx.x == 0) { float v = c3[0]; sw[O_C3] = pk2(v,v); }
    __syncthreads();

    int t = blockIdx.x * 128 + threadIdx.x;
    if (t >= nhalf) return;
    const float* p0 = inp + (size_t)(2 * t) * 385;
    const float* p1 = p0 + 385;

    // V1 accumulator (vision @ V1), built incrementally as sight values appear
    u64 acc[32];
    #pragma unroll
    for (int j = 0; j < 32; j++) acc[j] = 0ull;

    // window pairs: (x, yy) and (x, yy+1), x in 0..5, yy in {0,2,4}
    #pragma unroll 1
    for (int wp = 0; wp < 18; wp++) {
        int x  = wp / 3;
        int yy = (wp - x * 3) * 2;
        int cbase = x * 48 + yy * 6;

        u64 ha[12], hb[12];
        #pragma unroll
        for (int n = 0; n < 12; n++) { ha[n] = sw[O_B1 + n]; hb[n] = ha[n]; }

        // layer 1: conv 54 -> 12 for both windows of the pair
        #pragma unroll 1
        for (int ox = 0; ox < 3; ox++) {
            const float* r0 = p0 + cbase + ox * 48;
            const float* r1 = p1 + cbase + ox * 48;
            const u64* wk = sw + O_W1 + ox * 18 * 12;
            // the 18 inputs of window a are contiguous; window b is offset +6
            #pragma unroll 6
            for (int k = 0; k < 18; k++) {
                u64 va = pk2(__ldg(r0 + k),     __ldg(r1 + k));
                u64 vb = pk2(__ldg(r0 + k + 6), __ldg(r1 + k + 6));
                #pragma unroll
                for (int n = 0; n < 12; n++) {
                    u64 wv = wk[k * 12 + n];
                    ha[n] = fma2(va, wv, ha[n]);
                    hb[n] = fma2(vb, wv, hb[n]);
                }
            }
        }
        #pragma unroll
        for (int n = 0; n < 12; n++) { ha[n] = clamp2(ha[n]); hb[n] = clamp2(hb[n]); }

        // layer 2: 12 -> 12
        u64 ga[12], gb[12];
        #pragma unroll
        for (int n = 0; n < 12; n++) { ga[n] = sw[O_B2 + n]; gb[n] = ga[n]; }
        #pragma unroll 4
        for (int k = 0; k < 12; k++) {
            #pragma unroll
            for (int n = 0; n < 12; n++) {
                u64 wv = sw[O_W2 + k * 12 + n];
                ga[n] = fma2(ha[k], wv, ga[n]);
                gb[n] = fma2(hb[k], wv, gb[n]);
            }
        }
        #pragma unroll
        for (int n = 0; n < 12; n++) { ga[n] = clamp2(ga[n]); gb[n] = clamp2(gb[n]); }

        // layer 3: 12 -> 4
        u64 sa[4], sb[4];
        #pragma unroll
        for (int q = 0; q < 4; q++) { sa[q] = sw[O_B3 + q]; sb[q] = sa[q]; }
        #pragma unroll
        for (int k = 0; k < 12; k++) {
            #pragma unroll
            for (int q = 0; q < 4; q++) {
                u64 wv = sw[O_W3 + k * 4 + q];
                sa[q] = fma2(ga[k], wv, sa[q]);
                sb[q] = fma2(gb[k], wv, sb[q]);
            }
        }
        #pragma unroll
        for (int q = 0; q < 4; q++) { sa[q] = clamp2(sa[q]); sb[q] = clamp2(sb[q]); }

        // fold sight values into the V1 accumulator: rows (wa*4+q) and (wb*4+q)
        const u64* v1p = sw + O_V1 + (x * 6 + yy) * 4 * 32;
        #pragma unroll
        for (int q = 0; q < 4; q++) {
            #pragma unroll
            for (int j = 0; j < 32; j++) {
                acc[j] = fma2(sa[q], v1p[q * 32 + j],        acc[j]);
                acc[j] = fma2(sb[q], v1p[(4 + q) * 32 + j],  acc[j]);
            }
        }
    }

    // vision[144] = inp[:,384]; finish V1, add c1, clamp -> e1
    u64 last = pk2(__ldg(p0 + 384), __ldg(p1 + 384));
    const u64* v1l = sw + O_V1 + 144 * 32;
    u64 e1[32];
    #pragma unroll
    for (int j = 0; j < 32; j++) {
        u64 v = fma2(last, v1l[j], acc[j]);
        e1[j] = clamp2(add2(v, sw[O_C1 + j]));
    }

    // V2 (32->32) + V3 (32->1) fused: never materialize e2
    u64 o = sw[O_C3];
    #pragma unroll 1
    for (int j = 0; j < 32; j++) {
        u64 e = sw[O_C2 + j];
        #pragma unroll
        for (int k = 0; k < 32; k++) {
            float w = sV2[k * 32 + j];
            e = fma2(e1[k], pk2(w, w), e);
        }
        e = clamp2(e);
        o = fma2(e, sw[O_V3 + j], o);
    }
    o = clamp2(o);

    reinterpret_cast<float2*>(out)[t] = up2(o);
}

extern "C" void kernel_launch(void* const* d_in, const int* in_sizes, int n_in,
                              void* d_out, int out_size) {
    const float* inp = (const float*)d_in[0];
    const float* W1  = (const float*)d_in[1];
    const float* b1  = (const float*)d_in[2];
    const float* W2  = (const float*)d_in[3];
    const float* b2  = (const float*)d_in[4];
    const float* W3  = (const float*)d_in[5];
    const float* b3  = (const float*)d_in[6];
    const float* V1  = (const float*)d_in[7];
    const float* c1  = (const float*)d_in[8];
    const float* V2  = (const float*)d_in[9];
    const float* c2  = (const float*)d_in[10];
    const float* V3  = (const float*)d_in[11];
    const float* c3  = (const float*)d_in[12];

    int B = in_sizes[0] / 385;
    int nhalf = B / 2;  // B = 131072 (even); 2 samples per thread packed in f32x2
    int blocks = (nhalf + 127) / 128;

    lila_kernel<<<blocks, 128>>>(inp, W1, b1, W2, b2, W3, b3,
                                 V1, c1, V2, c2, V3, c3,
                                 (float*)d_out, nhalf);
}

// round 3
// speedup vs baseline: 1.1910x; 1.1910x over previous
#include <cuda_runtime.h>

typedef unsigned long long u64;

__device__ __forceinline__ u64 pk2(float lo, float hi) {
    u64 r; asm("mov.b64 %0,{%1,%2};" : "=l"(r) : "f"(lo), "f"(hi)); return r;
}
__device__ __forceinline__ float2 up2(u64 v) {
    float2 f; asm("mov.b64 {%0,%1},%2;" : "=f"(f.x), "=f"(f.y) : "l"(v)); return f;
}
__device__ __forceinline__ u64 fma2(u64 a, u64 b, u64 c) {
    u64 d; asm("fma.rn.f32x2 %0,%1,%2,%3;" : "=l"(d) : "l"(a), "l"(b), "l"(c)); return d;
}
__device__ __forceinline__ u64 add2(u64 a, u64 b) {
    u64 d; asm("add.rn.f32x2 %0,%1,%2;" : "=l"(d) : "l"(a), "l"(b)); return d;
}
__device__ __forceinline__ u64 clamp2(u64 v) {
    float2 f = up2(v);
    f.x = fminf(fmaxf(f.x, -1.0f), 1.0f);
    f.y = fminf(fmaxf(f.y, -1.0f), 1.0f);
    return pk2(f.x, f.y);
}

// shared-memory u64 (duplicated-pair) layout
#define O_W1 0        // 648  (54x12)
#define O_B1 648      // 12
#define O_W2 660      // 144  (12x12)
#define O_B2 804      // 12
#define O_W3 816      // 48   (12x4)
#define O_B3 864      // 4
#define O_V1 868      // 4640 (145x32)
#define O_C1 5508     // 32
#define O_C2 5540     // 32
#define O_V3 5572     // 32
#define O_C3 5604     // 1
#define N_U64 5605    // 44840 bytes

__global__ void __launch_bounds__(128, 3) lila_kernel(
    const float* __restrict__ inp,
    const float* __restrict__ W1, const float* __restrict__ b1,
    const float* __restrict__ W2, const float* __restrict__ b2,
    const float* __restrict__ W3, const float* __restrict__ b3,
    const float* __restrict__ V1, const float* __restrict__ c1,
    const float* __restrict__ V2, const float* __restrict__ c2,
    const float* __restrict__ V3, const float* __restrict__ c3,
    float* __restrict__ out, int nhalf)
{
    __shared__ u64  sw[N_U64];   // 44840 B (weights duplicated as {w,w})
    __shared__ float sV2[1024];  // 4096 B

    for (int i = threadIdx.x; i < 648;  i += 128) { float v = W1[i]; sw[O_W1+i] = pk2(v,v); }
    for (int i = threadIdx.x; i < 12;   i += 128) { float v = b1[i]; sw[O_B1+i] = pk2(v,v);
                                                    float u = b2[i]; sw[O_B2+i] = pk2(u,u); }
    for (int i = threadIdx.x; i < 144;  i += 128) { float v = W2[i]; sw[O_W2+i] = pk2(v,v); }
    for (int i = threadIdx.x; i < 48;   i += 128) { float v = W3[i]; sw[O_W3+i] = pk2(v,v); }
    for (int i = threadIdx.x; i < 4;    i += 128) { float v = b3[i]; sw[O_B3+i] = pk2(v,v); }
    for (int i = threadIdx.x; i < 4640; i += 128) { float v = V1[i]; sw[O_V1+i] = pk2(v,v); }
    for (int i = threadIdx.x; i < 32;   i += 128) { float v = c1[i]; sw[O_C1+i] = pk2(v,v);
                                                    float u = c2[i]; sw[O_C2+i] = pk2(u,u);
                                                    float w = V3[i]; sw[O_V3+i] = pk2(w,w); }
    for (int i = threadIdx.x; i < 1024; i += 128) { sV2[i] = V2[i]; }
    if (threadIdx.x == 0) { float v = c3[0]; sw[O_C3] = pk2(v,v); }
    __syncthreads();

    int t = blockIdx.x * 128 + threadIdx.x;
    if (t >= nhalf) return;
    const float* p0 = inp + (size_t)(2 * t) * 385;   // even word offset -> 8B aligned
    const float* p1 = p0 + 385;                      // odd word offset  -> NOT 8B aligned

    u64 acc[32];
    #pragma unroll
    for (int j = 0; j < 32; j++) acc[j] = 0ull;

    // window pairs: (x, yy) and (x, yy+1), x in 0..5, yy in {0,2,4}
    #pragma unroll 1
    for (int wp = 0; wp < 18; wp++) {
        int x  = wp / 3;
        int yy = (wp - x * 3) * 2;
        int cbase = x * 48 + yy * 6;

        u64 ha[12], hb[12];
        #pragma unroll
        for (int n = 0; n < 12; n++) { ha[n] = sw[O_B1 + n]; hb[n] = ha[n]; }

        // layer 1: both windows of the pair need cols [cbase+ox*48 .. +23].
        // Sample 0: 12 aligned float2 loads. Sample 1 (odd base): 13 float2
        // loads from (r1-1), aligned, with carry elements across phases.
        #pragma unroll 1
        for (int ox = 0; ox < 3; ox++) {
            const float*  r0 = p0 + cbase + ox * 48;
            const float*  r1 = p1 + cbase + ox * 48;
            const float2* q0 = reinterpret_cast<const float2*>(r0);
            const float2* q1 = reinterpret_cast<const float2*>(r1 - 1);
            const u64* wk = sw + O_W1 + ox * 216;

            u64 v[12];
            float carry;
            {
                float2 A0=__ldg(q0+0),A1=__ldg(q0+1),A2=__ldg(q0+2),
                       A3=__ldg(q0+3),A4=__ldg(q0+4),A5=__ldg(q0+5);
                float2 B0=__ldg(q1+0),B1=__ldg(q1+1),B2=__ldg(q1+2),B3=__ldg(q1+3),
                       B4=__ldg(q1+4),B5=__ldg(q1+5),B6=__ldg(q1+6);
                v[0]=pk2(A0.x,B0.y);  v[1]=pk2(A0.y,B1.x);
                v[2]=pk2(A1.x,B1.y);  v[3]=pk2(A1.y,B2.x);
                v[4]=pk2(A2.x,B2.y);  v[5]=pk2(A2.y,B3.x);
                v[6]=pk2(A3.x,B3.y);  v[7]=pk2(A3.y,B4.x);
                v[8]=pk2(A4.x,B4.y);  v[9]=pk2(A4.y,B5.x);
                v[10]=pk2(A5.x,B5.y); v[11]=pk2(A5.y,B6.x);
                carry = B6.y;  // sample-b col 12
            }
            // phase 0: k = 0..5
            #pragma unroll
            for (int kk = 0; kk < 6; kk++) {
                u64 va = v[kk], vb = v[kk + 6];
                #pragma unroll
                for (int n = 0; n < 12; n++) {
                    u64 wv = wk[kk * 12 + n];
                    ha[n] = fma2(va, wv, ha[n]);
                    hb[n] = fma2(vb, wv, hb[n]);
                }
            }
            // phase 1: cols 12..17
            {
                #pragma unroll
                for (int i = 0; i < 6; i++) v[i] = v[i + 6];
                float2 A6=__ldg(q0+6),A7=__ldg(q0+7),A8=__ldg(q0+8);
                float2 B7=__ldg(q1+7),B8=__ldg(q1+8),B9=__ldg(q1+9);
                v[6] =pk2(A6.x,carry); v[7] =pk2(A6.y,B7.x);
                v[8] =pk2(A7.x,B7.y);  v[9] =pk2(A7.y,B8.x);
                v[10]=pk2(A8.x,B8.y);  v[11]=pk2(A8.y,B9.x);
                carry = B9.y;  // sample-b col 18
            }
            #pragma unroll
            for (int kk = 0; kk < 6; kk++) {
                u64 va = v[kk], vb = v[kk + 6];
                #pragma unroll
                for (int n = 0; n < 12; n++) {
                    u64 wv = wk[(6 + kk) * 12 + n];
                    ha[n] = fma2(va, wv, ha[n]);
                    hb[n] = fma2(vb, wv, hb[n]);
                }
            }
            // phase 2: cols 18..23
            {
                #pragma unroll
                for (int i = 0; i < 6; i++) v[i] = v[i + 6];
                float2 A9=__ldg(q0+9),A10=__ldg(q0+10),A11=__ldg(q0+11);
                float2 B10=__ldg(q1+10),B11=__ldg(q1+11),B12=__ldg(q1+12);
                v[6] =pk2(A9.x,carry);  v[7] =pk2(A9.y,B10.x);
                v[8] =pk2(A10.x,B10.y); v[9] =pk2(A10.y,B11.x);
                v[10]=pk2(A11.x,B11.y); v[11]=pk2(A11.y,B12.x);
            }
            #pragma unroll
            for (int kk = 0; kk < 6; kk++) {
                u64 va = v[kk], vb = v[kk + 6];
                #pragma unroll
                for (int n = 0; n < 12; n++) {
                    u64 wv = wk[(12 + kk) * 12 + n];
                    ha[n] = fma2(va, wv, ha[n]);
                    hb[n] = fma2(vb, wv, hb[n]);
                }
            }
        }
        #pragma unroll
        for (int n = 0; n < 12; n++) { ha[n] = clamp2(ha[n]); hb[n] = clamp2(hb[n]); }

        // layer 2: 12 -> 12
        u64 ga[12], gb[12];
        #pragma unroll
        for (int n = 0; n < 12; n++) { ga[n] = sw[O_B2 + n]; gb[n] = ga[n]; }
        #pragma unroll 4
        for (int k = 0; k < 12; k++) {
            #pragma unroll
            for (int n = 0; n < 12; n++) {
                u64 wv = sw[O_W2 + k * 12 + n];
                ga[n] = fma2(ha[k], wv, ga[n]);
                gb[n] = fma2(hb[k], wv, gb[n]);
            }
        }
        #pragma unroll
        for (int n = 0; n < 12; n++) { ga[n] = clamp2(ga[n]); gb[n] = clamp2(gb[n]); }

        // layer 3: 12 -> 4
        u64 sa[4], sb[4];
        #pragma unroll
        for (int q = 0; q < 4; q++) { sa[q] = sw[O_B3 + q]; sb[q] = sa[q]; }
        #pragma unroll
        for (int k = 0; k < 12; k++) {
            #pragma unroll
            for (int q = 0; q < 4; q++) {
                u64 wv = sw[O_W3 + k * 4 + q];
                sa[q] = fma2(ga[k], wv, sa[q]);
                sb[q] = fma2(gb[k], wv, sb[q]);
            }
        }
        #pragma unroll
        for (int q = 0; q < 4; q++) { sa[q] = clamp2(sa[q]); sb[q] = clamp2(sb[q]); }

        // fold sight into the V1 accumulator: rows (wa*4+q), (wb*4+q)
        const u64* v1p = sw + O_V1 + (x * 6 + yy) * 4 * 32;
        #pragma unroll
        for (int q = 0; q < 4; q++) {
            #pragma unroll
            for (int j = 0; j < 32; j++) {
                acc[j] = fma2(sa[q], v1p[q * 32 + j],       acc[j]);
                acc[j] = fma2(sb[q], v1p[(4 + q) * 32 + j], acc[j]);
            }
        }
    }

    // vision[144] = inp[:,384]; finish V1, add c1, clamp -> e1
    u64 last = pk2(__ldg(p0 + 384), __ldg(p1 + 384));
    const u64* v1l = sw + O_V1 + 144 * 32;
    u64 e1[32];
    #pragma unroll
    for (int j = 0; j < 32; j++) {
        u64 v = fma2(last, v1l[j], acc[j]);
        e1[j] = clamp2(add2(v, sw[O_C1 + j]));
    }

    // V2 (32->32) + V3 (32->1) fused
    u64 o = sw[O_C3];
    #pragma unroll 1
    for (int j = 0; j < 32; j++) {
        u64 e = sw[O_C2 + j];
        #pragma unroll
        for (int k = 0; k < 32; k++) {
            float w = sV2[k * 32 + j];
            e = fma2(e1[k], pk2(w, w), e);
        }
        e = clamp2(e);
        o = fma2(e, sw[O_V3 + j], o);
    }
    o = clamp2(o);

    reinterpret_cast<float2*>(out)[t] = up2(o);
}

extern "C" void kernel_launch(void* const* d_in, const int* in_sizes, int n_in,
                              void* d_out, int out_size) {
    const float* inp = (const float*)d_in[0];
    const float* W1  = (const float*)d_in[1];
    const float* b1  = (const float*)d_in[2];
    const float* W2  = (const float*)d_in[3];
    const float* b2  = (const float*)d_in[4];
    const float* W3  = (const float*)d_in[5];
    const float* b3  = (const float*)d_in[6];
    const float* V1  = (const float*)d_in[7];
    const float* c1  = (const float*)d_in[8];
    const float* V2  = (const float*)d_in[9];
    const float* c2  = (const float*)d_in[10];
    const float* V3  = (const float*)d_in[11];
    const float* c3  = (const float*)d_in[12];

    int B = in_sizes[0] / 385;
    int nhalf = B / 2;
    int blocks = (nhalf + 127) / 128;

    lila_kernel<<<blocks, 128>>>(inp, W1, b1, W2, b2, W3, b3,
                                 V1, c1, V2, c2, V3, c3,
                                 (float*)d_out, nhalf);
}